// round 8
// baseline (speedup 1.0000x reference)
#include <cuda_runtime.h>
#include <cstdint>

// Problem dims (fixed by setup_inputs)
#define C_DIM   4096
#define K_DIM   4096
#define M_TOT   8192            // B*X = 2*4096
#define NBLK    128             // C / 32

// GEMM tiling: 256x128 CTA tile, 512 threads = 16 warps (4m x 4n), warp tile 64x32
#define BM      256
#define BN      128
#define BK      32
#define STAGES  4
#define KITERS  (C_DIM / BK)    // 128
#define THREADS 512

// Per-stage smem tiles (swizzled row-major, 128B rows)
#define A_STAGE_BYTES   (BM * BK * 4)              // 32768
#define B_STAGE_BYTES   (BN * BK * 4)              // 16384
#define STAGE_BYTES     (A_STAGE_BYTES + B_STAGE_BYTES)
#define SMEM_TOTAL      (STAGES * STAGE_BYTES)     // 196608

// Dequantized, tf32-rounded scratch. Static device globals (allocation-free).
__device__ float g_A[(size_t)M_TOT * C_DIM];   // 128 MiB
__device__ float g_B[(size_t)K_DIM * C_DIM];   //  64 MiB

// ---------------------------------------------------------------------------
// Helpers (base-ISA PTX only)
// ---------------------------------------------------------------------------

__device__ __forceinline__ float tf32_rna(float x) {
    uint32_t u;
    asm("cvt.rna.tf32.f32 %0, %1;" : "=r"(u) : "f"(x));
    return __uint_as_float(u);
}

__device__ __forceinline__ void cp_async16(uint32_t smem_addr, const void* gptr) {
    asm volatile("cp.async.cg.shared.global [%0], [%1], 16;"
                 :: "r"(smem_addr), "l"(gptr) : "memory");
}
__device__ __forceinline__ void cp_commit() {
    asm volatile("cp.async.commit_group;" ::: "memory");
}
template <int N>
__device__ __forceinline__ void cp_wait() {
    asm volatile("cp.async.wait_group %0;" :: "n"(N) : "memory");
}

// m16n8k8 tf32 MMA, fp32 accumulate
__device__ __forceinline__ void mma_16n8k8(float* d, const float* a, const float* b) {
    asm volatile(
        "mma.sync.aligned.m16n8k8.row.col.f32.tf32.tf32.f32 "
        "{%0,%1,%2,%3}, {%4,%5,%6,%7}, {%8,%9}, {%0,%1,%2,%3};"
        : "+f"(d[0]), "+f"(d[1]), "+f"(d[2]), "+f"(d[3])
        : "r"(__float_as_uint(a[0])), "r"(__float_as_uint(a[1])),
          "r"(__float_as_uint(a[2])), "r"(__float_as_uint(a[3])),
          "r"(__float_as_uint(b[0])), "r"(__float_as_uint(b[1])));
}

// Swizzled byte offset: row-major, 128B rows, chunk-XOR swizzle.
__device__ __forceinline__ uint32_t sw_off(uint32_t row, uint32_t colf) {
    return row * 128u + ((colf * 4u) ^ ((row & 7u) << 4));
}

// ---------------------------------------------------------------------------
// Fused dequant pre-pass for BOTH tensors (one launch -> ncu captures GEMM).
// dst = round_rna_tf32(src * scale[block]); rows of 4096 floats, blocks of 32.
// ---------------------------------------------------------------------------
__global__ void dequant2_kernel(const float* __restrict__ x,
                                const float* __restrict__ sx,
                                const float* __restrict__ w,
                                const float* __restrict__ sw_,
                                float* __restrict__ dA,
                                float* __restrict__ dB,
                                int n4A, int n4tot) {
    int i = blockIdx.x * blockDim.x + threadIdx.x;
    if (i >= n4tot) return;
    const float* src;  const float* scale;  float* dst;  int idx;
    if (i < n4A) { src = x; scale = sx;  dst = dA; idx = i; }
    else         { src = w; scale = sw_; dst = dB; idx = i - n4A; }
    int row = idx >> 10;          // 1024 float4 per 4096-float row
    int c4  = idx & 1023;
    float s = __ldg(&scale[row * NBLK + (c4 >> 3)]);
    float4 v = reinterpret_cast<const float4*>(src)[idx];
    float4 o;
    o.x = tf32_rna(v.x * s);
    o.y = tf32_rna(v.y * s);
    o.z = tf32_rna(v.z * s);
    o.w = tf32_rna(v.w * s);
    reinterpret_cast<float4*>(dst)[idx] = o;
}

// ---------------------------------------------------------------------------
// mma.sync tf32 GEMM: out[m,n] = sum_c A[m,c]*B[n,c] + bias[n]
// Grid (K/BN, M/BM) = (32, 32). 512 threads = 16 warps (4 warps/SMSP for
// latency hiding), warp tile 64x32. 4-stage cp.async, one barrier/iter.
// ---------------------------------------------------------------------------
__global__ void __launch_bounds__(THREADS, 1)
gemm_tf32_kernel(const float* __restrict__ gA,
                 const float* __restrict__ gB,
                 const float* __restrict__ bias,
                 float* __restrict__ out) {
    extern __shared__ char smem[];
    const uint32_t smem_u32 = (uint32_t)__cvta_generic_to_shared(smem);

    const int tid  = threadIdx.x;
    const int lane = tid & 31;
    const int wid  = tid >> 5;            // 0..15
    const int wm0  = (wid & 3) * 64;      // warp row offset (4 m-warps)
    const int wn0  = (wid >> 2) * 32;     // warp col offset (4 n-warps)

    const int tileN = blockIdx.x;
    const int tileM = blockIdx.y;
    const size_t rowA0 = (size_t)tileM * BM;
    const size_t rowB0 = (size_t)tileN * BN;

    // -------- cp.async tile loader (per stage) --------
    // A: 256 rows x 8 chunks = 2048 -> 4/thread; B: 128 x 8 = 1024 -> 2/thread
    auto load_stage = [&](int s, int kit) {
        const uint32_t aBase = smem_u32 + s * STAGE_BYTES;
        const uint32_t bBase = aBase + A_STAGE_BYTES;
        const size_t kcol = (size_t)kit * BK;
        #pragma unroll
        for (int t = 0; t < 4; t++) {
            int idx = tid + t * THREADS;
            int r = idx >> 3, c = idx & 7;
            const float* src = gA + (rowA0 + r) * C_DIM + kcol + c * 4;
            cp_async16(aBase + r * 128 + ((c ^ (r & 7)) << 4), src);
        }
        #pragma unroll
        for (int t = 0; t < 2; t++) {
            int idx = tid + t * THREADS;
            int r = idx >> 3, c = idx & 7;
            const float* src = gB + (rowB0 + r) * C_DIM + kcol + c * 4;
            cp_async16(bBase + r * 128 + ((c ^ (r & 7)) << 4), src);
        }
        cp_commit();
    };

    const int lr = lane >> 2;    // 0..7
    const int lc = lane & 3;     // 0..3

    // -------- accumulators: 4 m-frags x 4 n-frags --------
    float acc[4][4][4];
    #pragma unroll
    for (int i = 0; i < 4; i++)
        #pragma unroll
        for (int j = 0; j < 4; j++)
            #pragma unroll
            for (int r = 0; r < 4; r++) acc[i][j][r] = 0.0f;

    // -------- prologue: fill STAGES-1 stages --------
    load_stage(0, 0);
    load_stage(1, 1);
    load_stage(2, 2);

    // -------- mainloop: one barrier per iteration --------
    for (int it = 0; it < KITERS; it++) {
        cp_wait<STAGES - 2>();
        __syncthreads();

        if (it + STAGES - 1 < KITERS) load_stage((it + STAGES - 1) & (STAGES - 1),
                                                 it + STAGES - 1);
        else                          cp_commit();   // keep group count uniform

        const char* aTile = smem + (it & (STAGES - 1)) * STAGE_BYTES;
        const char* bTile = aTile + A_STAGE_BYTES;

        #pragma unroll
        for (int kk = 0; kk < 4; kk++) {
            const int k0 = kk * 8;
            float af[4][4], bf[4][2];
            #pragma unroll
            for (int i = 0; i < 4; i++) {
                const uint32_t r0 = wm0 + i * 16 + lr;
                af[i][0] = *(const float*)(aTile + sw_off(r0,     k0 + lc));
                af[i][1] = *(const float*)(aTile + sw_off(r0 + 8, k0 + lc));
                af[i][2] = *(const float*)(aTile + sw_off(r0,     k0 + lc + 4));
                af[i][3] = *(const float*)(aTile + sw_off(r0 + 8, k0 + lc + 4));
            }
            #pragma unroll
            for (int j = 0; j < 4; j++) {
                const uint32_t rn = wn0 + j * 8 + lr;
                bf[j][0] = *(const float*)(bTile + sw_off(rn, k0 + lc));
                bf[j][1] = *(const float*)(bTile + sw_off(rn, k0 + lc + 4));
            }
            #pragma unroll
            for (int i = 0; i < 4; i++)
                #pragma unroll
                for (int j = 0; j < 4; j++)
                    mma_16n8k8(acc[i][j], af[i], bf[j]);
        }
    }

    // -------- epilogue: bias add + store --------
    #pragma unroll
    for (int i = 0; i < 4; i++) {
        const size_t r0 = rowA0 + wm0 + i * 16 + lr;
        #pragma unroll
        for (int j = 0; j < 4; j++) {
            const size_t col = rowB0 + wn0 + j * 8 + lc * 2;
            const float2 b2 = *reinterpret_cast<const float2*>(bias + col);
            float2 o0, o1;
            o0.x = acc[i][j][0] + b2.x;
            o0.y = acc[i][j][1] + b2.y;
            o1.x = acc[i][j][2] + b2.x;
            o1.y = acc[i][j][3] + b2.y;
            *reinterpret_cast<float2*>(out + r0 * K_DIM + col)       = o0;
            *reinterpret_cast<float2*>(out + (r0 + 8) * K_DIM + col) = o1;
        }
    }
}

// ---------------------------------------------------------------------------
// Host
// ---------------------------------------------------------------------------
extern "C" void kernel_launch(void* const* d_in, const int* in_sizes, int n_in,
                              void* d_out, int out_size) {
    const float* x    = (const float*)d_in[0];   // (2, 4096, 4096)
    const float* w    = (const float*)d_in[1];   // (4096, 4096)
    const float* bias = (const float*)d_in[2];   // (4096,)
    const float* sx   = (const float*)d_in[3];   // (2, 4096, 128)
    const float* sw   = (const float*)d_in[4];   // (4096, 128)

    void* pA = nullptr;
    void* pB = nullptr;
    cudaGetSymbolAddress(&pA, g_A);
    cudaGetSymbolAddress(&pB, g_B);

    // Fused dequant pre-pass (one launch)
    int n4A   = M_TOT * C_DIM / 4;               // 8,388,608
    int n4tot = n4A + K_DIM * C_DIM / 4;         // 12,582,912
    dequant2_kernel<<<n4tot / 256, 256>>>(x, sx, w, sw,
                                          (float*)pA, (float*)pB, n4A, n4tot);

    // GEMM
    cudaFuncSetAttribute(gemm_tf32_kernel,
                         cudaFuncAttributeMaxDynamicSharedMemorySize, SMEM_TOTAL);
    dim3 grid(K_DIM / BN, M_TOT / BM);   // (32, 32)
    gemm_tf32_kernel<<<grid, THREADS, SMEM_TOTAL>>>((const float*)pA, (const float*)pB,
                                                    bias, (float*)d_out);
}

// round 15
// speedup vs baseline: 1.7454x; 1.7454x over previous
#include <cuda_runtime.h>
#include <cstdint>

// Problem dims (fixed by setup_inputs)
#define C_DIM   4096
#define K_DIM   4096
#define M_TOT   8192            // B*X = 2*4096
#define NBLK    128             // C / 32

// GEMM tiling (R6 proven config)
#define BM      128
#define BN      256
#define BK      32
#define STAGES  3
#define KITERS  (C_DIM / BK)    // 128

#define A_STAGE_BYTES   (BM * BK * 4)              // 16384
#define B_STAGE_BYTES   (BN * BK * 4)              // 32768
#define STAGE_BYTES     (A_STAGE_BYTES + B_STAGE_BYTES)
#define SMEM_TOTAL      (STAGES * STAGE_BYTES)     // 147456

// Fragment-ordered, tf32-rounded scratch (allocation-free device globals).
// g_A: [tileM(64)][it(128)][m16i(8)][kb(4)][lane(32)][4]  = 128 MiB
// g_B: [tileN(16)][it(128)][n8i(32)][kb(4)][lane(32)][2]  =  64 MiB
__device__ float g_A[(size_t)M_TOT * C_DIM];
__device__ float g_B[(size_t)K_DIM * C_DIM];

// ---------------------------------------------------------------------------
// Helpers (base-ISA PTX only)
// ---------------------------------------------------------------------------

__device__ __forceinline__ float tf32_rna(float x) {
    uint32_t u;
    asm("cvt.rna.tf32.f32 %0, %1;" : "=r"(u) : "f"(x));
    return __uint_as_float(u);
}

__device__ __forceinline__ void cp_async16(uint32_t smem_addr, const void* gptr) {
    asm volatile("cp.async.cg.shared.global [%0], [%1], 16;"
                 :: "r"(smem_addr), "l"(gptr) : "memory");
}
__device__ __forceinline__ void cp_commit() {
    asm volatile("cp.async.commit_group;" ::: "memory");
}
template <int N>
__device__ __forceinline__ void cp_wait() {
    asm volatile("cp.async.wait_group %0;" :: "n"(N) : "memory");
}

// m16n8k8 tf32 MMA, fp32 accumulate
__device__ __forceinline__ void mma_16n8k8(float* d, const float* a, const float* b) {
    asm volatile(
        "mma.sync.aligned.m16n8k8.row.col.f32.tf32.tf32.f32 "
        "{%0,%1,%2,%3}, {%4,%5,%6,%7}, {%8,%9}, {%0,%1,%2,%3};"
        : "+f"(d[0]), "+f"(d[1]), "+f"(d[2]), "+f"(d[3])
        : "r"(__float_as_uint(a[0])), "r"(__float_as_uint(a[1])),
          "r"(__float_as_uint(a[2])), "r"(__float_as_uint(a[3])),
          "r"(__float_as_uint(b[0])), "r"(__float_as_uint(b[1])));
}

// ---------------------------------------------------------------------------
// Fused dequant + fragment-permute for BOTH tensors (single launch).
// Fragment order (m16n8k8.row.col):
//   A thread(lane): a0=(lr,lc) a1=(lr+8,lc) a2=(lr,lc+4) a3=(lr+8,lc+4)
//   B thread(lane): b0=(n=lr,k=lc) b1=(n=lr,k=lc+4)
// Scale block = 32 cols = exactly one k-iteration -> scale index is `it`.
// ---------------------------------------------------------------------------
#define N4A  8388608   // float4 chunks of g_A  (33,554,432 floats / 4)
#define N2B  8388608   // float2 chunks of g_B  (16,777,216 floats / 2)

__global__ void dequant_perm_kernel(const float* __restrict__ x,
                                    const float* __restrict__ sx,
                                    const float* __restrict__ w,
                                    const float* __restrict__ sw_,
                                    float* __restrict__ dA,
                                    float* __restrict__ dB) {
    unsigned t = blockIdx.x * blockDim.x + threadIdx.x;
    if (t < N4A) {
        // ---- A path: one float4 (a0..a3) per thread ----
        unsigned lane = t & 31u;
        unsigned lr = lane >> 2, lc = lane & 3u;
        unsigned kb   = (t >> 5) & 3u;
        unsigned m16i = (t >> 7) & 7u;
        unsigned it   = (t >> 10) & 127u;
        unsigned tM   = t >> 17;               // 0..63
        unsigned row0 = tM * 128u + m16i * 16u + lr;
        unsigned row1 = row0 + 8u;
        unsigned c0   = it * 32u + kb * 8u + lc;
        float s0 = __ldg(&sx[row0 * NBLK + it]);
        float s1 = __ldg(&sx[row1 * NBLK + it]);
        const float* r0p = x + (size_t)row0 * C_DIM;
        const float* r1p = x + (size_t)row1 * C_DIM;
        float4 o;
        o.x = tf32_rna(r0p[c0]     * s0);
        o.y = tf32_rna(r1p[c0]     * s1);
        o.z = tf32_rna(r0p[c0 + 4] * s0);
        o.w = tf32_rna(r1p[c0 + 4] * s1);
        reinterpret_cast<float4*>(dA)[t] = o;
    } else {
        // ---- B path: one float2 (b0,b1) per thread ----
        unsigned u = t - N4A;
        unsigned lane = u & 31u;
        unsigned lr = lane >> 2, lc = lane & 3u;
        unsigned kb  = (u >> 5) & 3u;
        unsigned n8i = (u >> 7) & 31u;
        unsigned it  = (u >> 12) & 127u;
        unsigned tN  = u >> 19;                // 0..15
        unsigned r   = tN * 256u + n8i * 8u + lr;
        unsigned c0  = it * 32u + kb * 8u + lc;
        float s = __ldg(&sw_[r * NBLK + it]);
        const float* rp = w + (size_t)r * C_DIM;
        float2 o;
        o.x = tf32_rna(rp[c0]     * s);
        o.y = tf32_rna(rp[c0 + 4] * s);
        reinterpret_cast<float2*>(dB)[u] = o;
    }
}

// ---------------------------------------------------------------------------
// mma.sync tf32 GEMM on fragment-ordered operands.
// Grid (K/BN, M/BM) = (16, 64). 256 threads = 8 warps (2m x 4n), 64x64 warp
// tiles. 3-stage cp.async (linear copies), fragment loads = LDS.128/LDS.64.
// ---------------------------------------------------------------------------
__global__ void __launch_bounds__(256, 1)
gemm_tf32_kernel(const float* __restrict__ gA,
                 const float* __restrict__ gB,
                 const float* __restrict__ bias,
                 float* __restrict__ out) {
    extern __shared__ char smem[];
    const uint32_t smem_u32 = (uint32_t)__cvta_generic_to_shared(smem);

    const int tid   = threadIdx.x;
    const int lane  = tid & 31;
    const int wid   = tid >> 5;
    const int wm0   = (wid & 1) * 64;     // warp row offset
    const int wn0   = (wid >> 1) * 64;    // warp col offset

    const int tileN = blockIdx.x;
    const int tileM = blockIdx.y;

    // -------- linear cp.async loader: fragment-ordered chunks --------
    auto load_stage = [&](int s, int kit) {
        const float* aSrc = gA + (((size_t)tileM * KITERS + kit) << 12);  // *4096
        const float* bSrc = gB + (((size_t)tileN * KITERS + kit) << 13);  // *8192
        const uint32_t aBase = smem_u32 + s * STAGE_BYTES;
        const uint32_t bBase = aBase + A_STAGE_BYTES;
        #pragma unroll
        for (int tcnt = 0; tcnt < 4; tcnt++)
            cp_async16(aBase + tid * 16 + tcnt * 4096, aSrc + tid * 4 + tcnt * 1024);
        #pragma unroll
        for (int tcnt = 0; tcnt < 8; tcnt++)
            cp_async16(bBase + tid * 16 + tcnt * 4096, bSrc + tid * 4 + tcnt * 1024);
        cp_commit();
    };

    // -------- accumulators --------
    float acc[4][8][4];
    #pragma unroll
    for (int i = 0; i < 4; i++)
        #pragma unroll
        for (int j = 0; j < 8; j++)
            #pragma unroll
            for (int r = 0; r < 4; r++) acc[i][j][r] = 0.0f;

    // -------- prologue --------
    load_stage(0, 0);
    load_stage(1, 1);

    const int m16base = wm0 >> 4;   // 0 or 4
    const int n8base  = wn0 >> 3;   // 0, 8, 16, 24

    // -------- mainloop (R6-proven structure) --------
    for (int it = 0; it < KITERS; it++) {
        cp_wait<1>();
        __syncthreads();

        if (it + 2 < KITERS) load_stage((it + 2) % STAGES, it + 2);
        else                 cp_commit();   // keep group count uniform

        const int s = it % STAGES;
        const char* aTile = smem + s * STAGE_BYTES;
        const char* bTile = aTile + A_STAGE_BYTES;

        #pragma unroll
        for (int kk = 0; kk < 4; kk++) {
            float4 af[4];
            float2 bf[8];
            #pragma unroll
            for (int i = 0; i < 4; i++)
                af[i] = *(const float4*)(aTile +
                        ((((m16base + i) * 4 + kk) * 32 + lane) << 4));
            #pragma unroll
            for (int j = 0; j < 8; j++)
                bf[j] = *(const float2*)(bTile +
                        ((((n8base + j) * 4 + kk) * 32 + lane) << 3));
            #pragma unroll
            for (int i = 0; i < 4; i++)
                #pragma unroll
                for (int j = 0; j < 8; j++)
                    mma_16n8k8(acc[i][j], &af[i].x, &bf[j].x);
        }
        __syncthreads();
    }

    // -------- epilogue: bias add + store --------
    const int lr = lane >> 2;
    const int lc = lane & 3;
    const size_t rowA0 = (size_t)tileM * BM;
    const size_t rowB0 = (size_t)tileN * BN;
    #pragma unroll
    for (int i = 0; i < 4; i++) {
        const size_t r0 = rowA0 + wm0 + i * 16 + lr;
        #pragma unroll
        for (int j = 0; j < 8; j++) {
            const size_t col = rowB0 + wn0 + j * 8 + lc * 2;
            const float2 b2 = *reinterpret_cast<const float2*>(bias + col);
            float2 o0, o1;
            o0.x = acc[i][j][0] + b2.x;
            o0.y = acc[i][j][1] + b2.y;
            o1.x = acc[i][j][2] + b2.x;
            o1.y = acc[i][j][3] + b2.y;
            *reinterpret_cast<float2*>(out + r0 * K_DIM + col)       = o0;
            *reinterpret_cast<float2*>(out + (r0 + 8) * K_DIM + col) = o1;
        }
    }
}

// ---------------------------------------------------------------------------
// Host
// ---------------------------------------------------------------------------
extern "C" void kernel_launch(void* const* d_in, const int* in_sizes, int n_in,
                              void* d_out, int out_size) {
    const float* x    = (const float*)d_in[0];   // (2, 4096, 4096)
    const float* w    = (const float*)d_in[1];   // (4096, 4096)
    const float* bias = (const float*)d_in[2];   // (4096,)
    const float* sx   = (const float*)d_in[3];   // (2, 4096, 128)
    const float* sw   = (const float*)d_in[4];   // (4096, 128)

    void* pA = nullptr;
    void* pB = nullptr;
    cudaGetSymbolAddress(&pA, g_A);
    cudaGetSymbolAddress(&pB, g_B);

    // Fused dequant + fragment-permute (single launch; 2 launches/call total
    // keeps ncu -s 5 -c 1 landing on the GEMM)
    dequant_perm_kernel<<<(N4A + N2B) / 256, 256>>>(x, sx, w, sw,
                                                    (float*)pA, (float*)pB);

    // GEMM
    cudaFuncSetAttribute(gemm_tf32_kernel,
                         cudaFuncAttributeMaxDynamicSharedMemorySize, SMEM_TOTAL);
    dim3 grid(K_DIM / BN, M_TOT / BM);   // (16, 64)
    gemm_tf32_kernel<<<grid, 256, SMEM_TOTAL>>>((const float*)pA, (const float*)pB,
                                                bias, (float*)d_out);
}